// round 4
// baseline (speedup 1.0000x reference)
#include <cuda_runtime.h>
#include <cuda_bf16.h>

// Problem dims (fixed): B=4, N=2048, F_in=128, H=4, D=32
#define Bn 4
#define Nn 2048
#define Fn 128
#define Hn 4
#define Dn 32
#define BH (Bn*Hn)

// Scratch (device globals; no allocation allowed). 16B+ alignment for float4 access.
__device__ __align__(256) float g_Wh[BH * Nn * Dn];   // [bh][n][d]  4 MB
__device__ __align__(16)  float g_es[BH * Nn];        // e_src
__device__ __align__(16)  float g_ed[BH * Nn];        // e_dst

// -------------------- Kernel A: projection + e_src/e_dst --------------------
// grid (B, N/16), 128 threads (4 warps = 4 heads, lane = d)
__global__ __launch_bounds__(128) void proj_kernel(
    const float* __restrict__ h, const float* __restrict__ W,
    const float* __restrict__ a)
{
    __shared__ __align__(16) float h_sm[16 * Fn];
    const int b  = blockIdx.x;
    const int n0 = blockIdx.y * 16;

    const float4* hsrc = (const float4*)(h + (size_t)(b * Nn + n0) * Fn);
    float4* hdst = (float4*)h_sm;
    #pragma unroll
    for (int r = 0; r < 4; r++) hdst[threadIdx.x + r * 128] = hsrc[threadIdx.x + r * 128];
    __syncthreads();

    const int warp = threadIdx.x >> 5;   // head
    const int lane = threadIdx.x & 31;   // d

    const float* Wp = W + (warp * Fn) * Dn + lane;
    float acc[16];
    #pragma unroll
    for (int n = 0; n < 16; n++) acc[n] = 0.f;

    #pragma unroll 4
    for (int f = 0; f < Fn; f++) {
        float w = __ldg(Wp + f * Dn);
        #pragma unroll
        for (int n = 0; n < 16; n++)
            acc[n] = fmaf(h_sm[n * Fn + f], w, acc[n]);
    }

    const float a_s = __ldg(a + warp * (2 * Dn) + lane);
    const float a_d = __ldg(a + warp * (2 * Dn) + Dn + lane);

    const int bh = b * Hn + warp;
    float* whp = g_Wh + ((size_t)bh * Nn + n0) * Dn + lane;

    #pragma unroll
    for (int n = 0; n < 16; n++) {
        whp[n * Dn] = acc[n];
        float es = acc[n] * a_s;
        float ed = acc[n] * a_d;
        #pragma unroll
        for (int off = 16; off; off >>= 1) {
            es += __shfl_xor_sync(0xffffffffu, es, off);
            ed += __shfl_xor_sync(0xffffffffu, ed, off);
        }
        if (lane == 0) {
            g_es[bh * Nn + n0 + n] = es;
            g_ed[bh * Nn + n0 + n] = ed;
        }
    }
}

// -------------------- Kernel B: masked-softmax (exact row max) + P@Wh --------------------
// grid (BH, N/16), 256 threads = 8 warps; each warp owns 2 rows i.
// Pass 1: scan adjacency once -> masked row-max of e_dst + per-lane adj bitmask (uint64).
// Pass 2: exp + FMA accumulation; adjacency from registers (no reload).
#define TJ 128          // j chunk for Wh staging
#define WPAD 36         // padded smem row stride (floats)

__global__ __launch_bounds__(256, 2) void attn_kernel(
    const int* __restrict__ adj, float* __restrict__ out)
{
    __shared__ __align__(16) float ed_full[Nn];        // 8 KB: e_dst row for this bh
    __shared__ __align__(16) float wh_sm[TJ * WPAD];   // 18 KB

    const int bh = blockIdx.x;
    const int b  = bh >> 2;
    const int hd = bh & 3;
    const int itile = blockIdx.y * 16;
    const int warp = threadIdx.x >> 5;
    const int lane = threadIdx.x & 31;
    const int i0 = itile + warp * 2;
    const int i1 = i0 + 1;

    const float es0 = g_es[bh * Nn + i0];
    const float es1 = g_es[bh * Nn + i1];

    // stage full e_dst row (2048 floats) once
    {
        const float4* src = (const float4*)(g_ed + bh * Nn);
        float4* dst = (float4*)ed_full;
        #pragma unroll
        for (int r = 0; r < 2; r++) dst[threadIdx.x + r * 256] = src[threadIdx.x + r * 256];
    }
    __syncthreads();

    // ---- Pass 1: masked row max + adjacency bit-pack ----
    const int* adj0 = adj + (size_t)i0 * Nn;
    const int* adj1 = adj + (size_t)i1 * Nn;
    unsigned long long bits0 = 0ull, bits1 = 0ull;
    float m0 = -__int_as_float(0x7f800000) * 0.f - 1e30f; // -1e30 sentinel
    float m1 = -1e30f;
    m0 = -1e30f;
    #pragma unroll 8
    for (int g = 0; g < 64; g++) {
        const int j = g * 32 + lane;
        const float ed = ed_full[j];
        if (__ldg(adj0 + j) > 0) { m0 = fmaxf(m0, ed); bits0 |= 1ull << g; }
        if (__ldg(adj1 + j) > 0) { m1 = fmaxf(m1, ed); bits1 |= 1ull << g; }
    }
    #pragma unroll
    for (int off = 16; off; off >>= 1) {
        m0 = fmaxf(m0, __shfl_xor_sync(0xffffffffu, m0, off));
        m1 = fmaxf(m1, __shfl_xor_sync(0xffffffffu, m1, off));
    }
    const bool empty0 = (m0 < -9e29f);
    const bool empty1 = (m1 < -9e29f);
    const float nz0 = empty0 ? 1.f : 0.f;   // empty row: uniform weights (matches reference)
    const float nz1 = empty1 ? 1.f : 0.f;
    float M0 = es0 + m0; M0 = (M0 > 0.f) ? M0 : 0.2f * M0;
    float M1 = es1 + m1; M1 = (M1 > 0.f) ? M1 : 0.2f * M1;
    if (empty0) M0 = 0.f;
    if (empty1) M1 = 0.f;

    // ---- Pass 2: exp + P@Wh ----
    float v0[Dn], v1[Dn];
    #pragma unroll
    for (int k = 0; k < Dn; k++) { v0[k] = 0.f; v1[k] = 0.f; }
    float l0 = 0.f, l1 = 0.f;

    const float* whg = g_Wh + (size_t)bh * Nn * Dn;

    for (int c = 0; c < Nn / TJ; c++) {
        const int jb = c * TJ;
        __syncthreads();
        // stage Wh chunk [TJ][32] -> wh_sm [TJ][WPAD] (float4, conflict-free)
        #pragma unroll
        for (int r = 0; r < 4; r++) {
            int i4  = threadIdx.x + r * 256;
            int row = i4 >> 3;
            int c4  = i4 & 7;
            float4 val = *(const float4*)(whg + (size_t)(jb + row) * Dn + c4 * 4);
            *(float4*)(wh_sm + row * WPAD + c4 * 4) = val;
        }
        __syncthreads();

        #pragma unroll
        for (int t = 0; t < 4; t++) {
            const int g = c * 4 + t;
            const float ed = ed_full[jb + t * 32 + lane];
            float s0 = es0 + ed; s0 = (s0 > 0.f) ? s0 : 0.2f * s0;
            float s1 = es1 + ed; s1 = (s1 > 0.f) ? s1 : 0.2f * s1;
            float p0 = ((bits0 >> g) & 1ull) ? __expf(s0 - M0) : nz0;
            float p1 = ((bits1 >> g) & 1ull) ? __expf(s1 - M1) : nz1;
            l0 += p0; l1 += p1;
            const float* wr = wh_sm + (t * 32 + lane) * WPAD;
            #pragma unroll
            for (int k = 0; k < 8; k++) {
                float4 w = *(const float4*)(wr + k * 4);
                v0[4*k+0] = fmaf(p0, w.x, v0[4*k+0]);
                v0[4*k+1] = fmaf(p0, w.y, v0[4*k+1]);
                v0[4*k+2] = fmaf(p0, w.z, v0[4*k+2]);
                v0[4*k+3] = fmaf(p0, w.w, v0[4*k+3]);
                v1[4*k+0] = fmaf(p1, w.x, v1[4*k+0]);
                v1[4*k+1] = fmaf(p1, w.y, v1[4*k+1]);
                v1[4*k+2] = fmaf(p1, w.z, v1[4*k+2]);
                v1[4*k+3] = fmaf(p1, w.w, v1[4*k+3]);
            }
        }
    }

    // Epilogue: per-d full-warp sums.
    #pragma unroll
    for (int off = 16; off; off >>= 1) {
        l0 += __shfl_xor_sync(0xffffffffu, l0, off);
        l1 += __shfl_xor_sync(0xffffffffu, l1, off);
    }
    float r0 = 0.f, r1 = 0.f;
    #pragma unroll
    for (int d = 0; d < Dn; d++) {
        float s0 = v0[d], s1 = v1[d];
        #pragma unroll
        for (int off = 16; off; off >>= 1) {
            s0 += __shfl_xor_sync(0xffffffffu, s0, off);
            s1 += __shfl_xor_sync(0xffffffffu, s1, off);
        }
        if (lane == d) { r0 = s0; r1 = s1; }
    }

    const float rl0 = 1.f / l0;   // l >= 1 (exact row max) or = N (empty row)
    const float rl1 = 1.f / l1;
    out[((size_t)(b * Nn + i0)) * (Hn * Dn) + hd * Dn + lane] = r0 * rl0;
    out[((size_t)(b * Nn + i1)) * (Hn * Dn) + hd * Dn + lane] = r1 * rl1;
}

extern "C" void kernel_launch(void* const* d_in, const int* in_sizes, int n_in,
                              void* d_out, int out_size)
{
    // Bind inputs by element count (robust to metadata ordering):
    //   h   : 4*2048*128 = 1048576 (float32)
    //   adj : 2048*2048  = 4194304 (int32)
    //   W   : 4*128*32   = 16384   (float32)
    //   a   : 4*64*1     = 256     (float32)
    const float* h = nullptr; const int* adj = nullptr;
    const float* W = nullptr; const float* a = nullptr;
    for (int i = 0; i < n_in; i++) {
        switch (in_sizes[i]) {
            case 1048576: h   = (const float*)d_in[i]; break;
            case 4194304: adj = (const int*)  d_in[i]; break;
            case 16384:   W   = (const float*)d_in[i]; break;
            case 256:     a   = (const float*)d_in[i]; break;
        }
    }
    float* out = (float*)d_out;

    proj_kernel<<<dim3(Bn, Nn / 16), 128>>>(h, W, a);
    attn_kernel<<<dim3(BH, Nn / 16), 256>>>(adj, out);
}